// round 3
// baseline (speedup 1.0000x reference)
#include <cuda_runtime.h>
#include <cstdint>

// ---------------------------------------------------------------------------
// Problem constants (fixed by the reference setup)
// ---------------------------------------------------------------------------
#define BS    2
#define QTOT  21760        // = V = sum of level areas
#define CEMB  256
#define HEADS 8
#define DH    32           // C / HEADS
#define LVLS  4
#define PTS   4
#define MTOT  (BS * QTOT)  // 43520 rows for all GEMMs

// level geometry: (128,128),(64,64),(32,32),(16,16)
__device__ __constant__ int c_lvl_wh[LVLS]    = {128, 64, 32, 16};
__device__ __constant__ int c_lvl_start[LVLS] = {0, 16384, 20480, 21504};

// ---------------------------------------------------------------------------
// Scratch (static device globals; no runtime allocation)
// ---------------------------------------------------------------------------
__device__ float g_val [(size_t)BS * QTOT * CEMB];   // [b][h][v][d]
__device__ float g_off [(size_t)BS * QTOT * CEMB];   // [b][q][256]
__device__ float g_attn[(size_t)BS * QTOT * 128];    // [b][q][128] logits
__device__ float g_mid [(size_t)BS * QTOT * CEMB];   // [b][q][c]   sampled

// ---------------------------------------------------------------------------
// Tiled SGEMM: C = A(MxK) @ B(KxN) + bias, 128x128 tile, BK=16, 8x8 per thread
// mode 0: C row-major [M][N]
// mode 1: permuted "val" layout: row=(b,v), col=(h,d) -> [((b*H+h)*V+v)*32+d]
// Requires M%128==0, N%128==0, K%16==0 (true here).
// ---------------------------------------------------------------------------
#define BM 128
#define BN 128
#define BK 16
#define TM 8
#define TN 8

__global__ __launch_bounds__(256, 2)
void sgemm_kernel(const float* __restrict__ A, const float* __restrict__ B,
                  const float* __restrict__ bias, float* __restrict__ C,
                  int M, int N, int K, int mode)
{
    __shared__ float As[BK][BM + 4];
    __shared__ float Bs[BK][BN];

    const int tid       = threadIdx.x;
    const int block_row = blockIdx.y * BM;
    const int block_col = blockIdx.x * BN;

    const int tx = tid & 15;   // 16 thread-cols
    const int ty = tid >> 4;   // 16 thread-rows

    float acc[TM][TN];
    #pragma unroll
    for (int i = 0; i < TM; i++)
        #pragma unroll
        for (int j = 0; j < TN; j++) acc[i][j] = 0.f;

    // A tile loads: 128x16 floats = 512 float4; 2 per thread
    const int a_row  = tid >> 2;          // 0..63 (+64)
    const int a_col4 = (tid & 3) * 4;     // 0,4,8,12
    // B tile loads: 16x128 floats = 512 float4; 2 per thread
    const int b_row  = tid >> 5;          // 0..7 (+8)
    const int b_col4 = (tid & 31) * 4;    // 0..124

    for (int k0 = 0; k0 < K; k0 += BK) {
        #pragma unroll
        for (int i = 0; i < 2; i++) {
            int r = a_row + i * 64;
            float4 v = *(const float4*)(A + (size_t)(block_row + r) * K + k0 + a_col4);
            As[a_col4 + 0][r] = v.x;
            As[a_col4 + 1][r] = v.y;
            As[a_col4 + 2][r] = v.z;
            As[a_col4 + 3][r] = v.w;
        }
        #pragma unroll
        for (int i = 0; i < 2; i++) {
            int r = b_row + i * 8;
            float4 v = *(const float4*)(B + (size_t)(k0 + r) * N + block_col + b_col4);
            *(float4*)&Bs[r][b_col4] = v;
        }
        __syncthreads();

        #pragma unroll
        for (int kk = 0; kk < BK; kk++) {
            float ar[TM], br[TN];
            #pragma unroll
            for (int i = 0; i < TM; i++) ar[i] = As[kk][ty * TM + i];
            #pragma unroll
            for (int j = 0; j < TN; j++) br[j] = Bs[kk][tx * TN + j];
            #pragma unroll
            for (int i = 0; i < TM; i++)
                #pragma unroll
                for (int j = 0; j < TN; j++)
                    acc[i][j] = fmaf(ar[i], br[j], acc[i][j]);
        }
        __syncthreads();
    }

    // epilogue
    #pragma unroll
    for (int i = 0; i < TM; i++) {
        int row = block_row + ty * TM + i;
        #pragma unroll
        for (int j = 0; j < TN; j++) {
            int col = block_col + tx * TN + j;
            float v = acc[i][j] + bias[col];
            if (mode == 0) {
                C[(size_t)row * N + col] = v;
            } else {
                int b = row / QTOT, q = row - b * QTOT;
                int h = col >> 5,  dc = col & 31;
                C[(((size_t)(b * HEADS + h)) * QTOT + q) * DH + dc] = v;
            }
        }
    }
}

// ---------------------------------------------------------------------------
// Sampler: one block per (b,q); warp = head, lane = channel.
// Reads g_off, g_attn (softmax over 16 per head), gathers from g_val,
// writes g_mid[b][q][h*32+d].
// ---------------------------------------------------------------------------
__global__ __launch_bounds__(256, 8)
void sample_kernel(const float* __restrict__ ref,
                   float* __restrict__ mid)
{
    const int bq = blockIdx.x;            // 0 .. BS*QTOT-1
    const int b  = bq / QTOT;
    const int t  = threadIdx.x;           // 256
    const int h  = t >> 5;
    const int dc = t & 31;

    __shared__ float s_off[256];
    __shared__ float s_w[128];
    __shared__ float s_ref[2 * LVLS];

    s_off[t] = g_off[(size_t)bq * 256 + t];
    if (t < 128) s_w[t] = g_attn[(size_t)bq * 128 + t];
    if (t < 2 * LVLS) s_ref[t] = ref[(size_t)bq * (2 * LVLS) + t];
    __syncthreads();

    // per-head softmax over 16 logits (8 threads, serial — cheap)
    if (t < HEADS) {
        float m = -1e30f;
        #pragma unroll
        for (int i = 0; i < 16; i++) m = fmaxf(m, s_w[t * 16 + i]);
        float s = 0.f;
        #pragma unroll
        for (int i = 0; i < 16; i++) {
            float e = expf(s_w[t * 16 + i] - m);
            s_w[t * 16 + i] = e;
            s += e;
        }
        float inv = 1.f / s;
        #pragma unroll
        for (int i = 0; i < 16; i++) s_w[t * 16 + i] *= inv;
    }
    __syncthreads();

    const float* valb = g_val + ((size_t)(b * HEADS + h)) * QTOT * DH + dc;

    float acc = 0.f;
    #pragma unroll
    for (int l = 0; l < LVLS; l++) {
        const int   W  = c_lvl_wh[l];
        const int   Hh = W;                       // square levels
        const int   st = c_lvl_start[l];
        const float fW = (float)W, fH = (float)Hh;
        const float rx = s_ref[l * 2 + 0];
        const float ry = s_ref[l * 2 + 1];
        #pragma unroll
        for (int p = 0; p < PTS; p++) {
            float ox = s_off[h * 32 + l * 8 + p * 2 + 0];
            float oy = s_off[h * 32 + l * 8 + p * 2 + 1];
            float aw = s_w[h * 16 + l * 4 + p];

            float x = (rx + ox / fW) * fW - 0.5f;
            float y = (ry + oy / fH) * fH - 0.5f;
            float x0f = floorf(x), y0f = floorf(y);
            int   x0 = (int)x0f,   y0 = (int)y0f;
            float fx = x - x0f,    fy = y - y0f;

            #pragma unroll
            for (int dy = 0; dy < 2; dy++) {
                int yi = y0 + dy;
                if (yi < 0 || yi >= Hh) continue;
                float wy = dy ? fy : (1.f - fy);
                #pragma unroll
                for (int dx = 0; dx < 2; dx++) {
                    int xi = x0 + dx;
                    if (xi < 0 || xi >= W) continue;
                    float w = (dx ? fx : (1.f - fx)) * wy * aw;
                    acc = fmaf(w, valb[(size_t)(st + yi * W + xi) * DH], acc);
                }
            }
        }
    }
    mid[(size_t)bq * 256 + t] = acc;
}

// ---------------------------------------------------------------------------
// Launch
// ---------------------------------------------------------------------------
extern "C" void kernel_launch(void* const* d_in, const int* in_sizes, int n_in,
                              void* d_out, int out_size)
{
    const float* query  = (const float*)d_in[0];
    const float* value  = (const float*)d_in[1];
    const float* refpts = (const float*)d_in[2];
    // d_in[3] = spatial_shapes (compile-time constants here)
    const float* W_off  = (const float*)d_in[4];
    const float* b_off  = (const float*)d_in[5];
    const float* W_attn = (const float*)d_in[6];
    const float* b_attn = (const float*)d_in[7];
    const float* W_v    = (const float*)d_in[8];
    const float* b_v    = (const float*)d_in[9];
    const float* W_out  = (const float*)d_in[10];
    const float* b_out  = (const float*)d_in[11];
    float* out = (float*)d_out;

    float *p_val, *p_off, *p_attn, *p_mid;
    cudaGetSymbolAddress((void**)&p_val,  g_val);
    cudaGetSymbolAddress((void**)&p_off,  g_off);
    cudaGetSymbolAddress((void**)&p_attn, g_attn);
    cudaGetSymbolAddress((void**)&p_mid,  g_mid);

    dim3 blk(256);
    dim3 grid256(CEMB / BN, MTOT / BM);   // (2, 340)
    dim3 grid128(128 / BN,  MTOT / BM);   // (1, 340)

    // 1) val = value @ W_v + b_v  -> [b][h][v][d] layout
    sgemm_kernel<<<grid256, blk>>>(value, W_v, b_v, p_val, MTOT, CEMB, CEMB, 1);
    // 2) off = query @ W_off + b_off
    sgemm_kernel<<<grid256, blk>>>(query, W_off, b_off, p_off, MTOT, CEMB, CEMB, 0);
    // 3) attn logits = query @ W_attn + b_attn
    sgemm_kernel<<<grid128, blk>>>(query, W_attn, b_attn, p_attn, MTOT, 128, CEMB, 0);
    // 4) deformable sampling -> g_mid
    sample_kernel<<<MTOT, blk>>>(refpts, p_mid);
    // 5) out = mid @ W_out + b_out
    sgemm_kernel<<<grid256, blk>>>(p_mid, W_out, b_out, out, MTOT, CEMB, CEMB, 0);
}

// round 4
// speedup vs baseline: 1.3728x; 1.3728x over previous
#include <cuda_runtime.h>
#include <cstdint>

// ---------------------------------------------------------------------------
// Problem constants (fixed by the reference setup)
// ---------------------------------------------------------------------------
#define BS    2
#define QTOT  21760        // = V = sum of level areas
#define CEMB  256
#define HEADS 8
#define DH    32           // C / HEADS
#define LVLS  4
#define PTS   4
#define MTOT  (BS * QTOT)  // 43520 rows for all GEMMs

__device__ __constant__ int c_lvl_wh[LVLS]    = {128, 64, 32, 16};
__device__ __constant__ int c_lvl_start[LVLS] = {0, 16384, 20480, 21504};

// ---------------------------------------------------------------------------
// Scratch (static device globals; no runtime allocation)
// ---------------------------------------------------------------------------
__device__ float g_val [(size_t)BS * QTOT * CEMB];   // [b][h][v][d]
__device__ float g_off [(size_t)BS * QTOT * CEMB];   // [b][q][256]
__device__ float g_attn[(size_t)BS * QTOT * 128];    // [b][q][128] logits
__device__ float g_mid [(size_t)BS * QTOT * CEMB];   // [b][q][c]   sampled

// ---------------------------------------------------------------------------
// Packed fp32x2 helpers (FFMA2 — 2x the scalar FFMA issue rate on sm_103a)
// ---------------------------------------------------------------------------
typedef unsigned long long u64;

__device__ __forceinline__ u64 pack2(float x, float y) {
    u64 r;
    asm("mov.b64 %0, {%1, %2};" : "=l"(r) : "f"(x), "f"(y));
    return r;
}
__device__ __forceinline__ float2 unpack2(u64 v) {
    float2 f;
    asm("mov.b64 {%0, %1}, %2;" : "=f"(f.x), "=f"(f.y) : "l"(v));
    return f;
}
__device__ __forceinline__ void fma2(u64& d, u64 a, u64 b) {
    asm("fma.rn.f32x2 %0, %1, %2, %3;" : "=l"(d) : "l"(a), "l"(b), "l"(d));
}

// ---------------------------------------------------------------------------
// Tiled SGEMM with packed f32x2 FMA: C = A(MxK) @ B(KxN) + bias
// 128x128 tile, BK=16, each thread: 8 rows (as 4 row-pairs) x 8 cols.
// mode 0: C row-major [M][N]
// mode 1: permuted "val" layout: row=(b,v), col=(h,d) -> [((b*H+h)*V+v)*32+d]
// ---------------------------------------------------------------------------
#define BM 128
#define BN 128
#define BK 16
#define TM 8
#define TN 8

__global__ __launch_bounds__(256, 2)
void sgemm2_kernel(const float* __restrict__ A, const float* __restrict__ B,
                   const float* __restrict__ bias, float* __restrict__ C,
                   int M, int N, int K, int mode)
{
    __shared__ float As[BK][BM + 4];
    __shared__ float Bs[BK][BN];

    const int tid       = threadIdx.x;
    const int block_row = blockIdx.y * BM;
    const int block_col = blockIdx.x * BN;

    const int tx = tid & 15;   // 16 thread-cols
    const int ty = tid >> 4;   // 16 thread-rows

    u64 acc2[4][8];            // row-pairs x cols
    #pragma unroll
    for (int i = 0; i < 4; i++)
        #pragma unroll
        for (int j = 0; j < 8; j++) acc2[i][j] = 0ull;

    // A tile loads: 128x16 floats = 512 float4; 2 per thread
    const int a_row  = tid >> 2;          // 0..63 (+64)
    const int a_col4 = (tid & 3) * 4;     // 0,4,8,12
    // B tile loads: 16x128 floats = 512 float4; 2 per thread
    const int b_row  = tid >> 5;          // 0..7 (+8)
    const int b_col4 = (tid & 31) * 4;    // 0..124

    for (int k0 = 0; k0 < K; k0 += BK) {
        #pragma unroll
        for (int i = 0; i < 2; i++) {
            int r = a_row + i * 64;
            float4 v = *(const float4*)(A + (size_t)(block_row + r) * K + k0 + a_col4);
            As[a_col4 + 0][r] = v.x;
            As[a_col4 + 1][r] = v.y;
            As[a_col4 + 2][r] = v.z;
            As[a_col4 + 3][r] = v.w;
        }
        #pragma unroll
        for (int i = 0; i < 2; i++) {
            int r = b_row + i * 8;
            float4 v = *(const float4*)(B + (size_t)(k0 + r) * N + block_col + b_col4);
            *(float4*)&Bs[r][b_col4] = v;
        }
        __syncthreads();

        #pragma unroll
        for (int kk = 0; kk < BK; kk++) {
            // A: 4 row-pairs, read as 64-bit (rows ty*8+2*i2, +1)
            u64 ar2[4];
            #pragma unroll
            for (int i = 0; i < 4; i++)
                ar2[i] = *(const u64*)&As[kk][ty * TM + i * 2];
            // B: 8 scalars -> splatted pairs
            float4 b0 = *(const float4*)&Bs[kk][tx * TN];
            float4 b1 = *(const float4*)&Bs[kk][tx * TN + 4];
            u64 br2[8];
            br2[0] = pack2(b0.x, b0.x); br2[1] = pack2(b0.y, b0.y);
            br2[2] = pack2(b0.z, b0.z); br2[3] = pack2(b0.w, b0.w);
            br2[4] = pack2(b1.x, b1.x); br2[5] = pack2(b1.y, b1.y);
            br2[6] = pack2(b1.z, b1.z); br2[7] = pack2(b1.w, b1.w);
            #pragma unroll
            for (int i = 0; i < 4; i++)
                #pragma unroll
                for (int j = 0; j < 8; j++)
                    fma2(acc2[i][j], ar2[i], br2[j]);
        }
        __syncthreads();
    }

    // epilogue
    #pragma unroll
    for (int i = 0; i < 4; i++) {
        int r0 = block_row + ty * TM + i * 2;
        int r1 = r0 + 1;
        #pragma unroll
        for (int j = 0; j < 8; j++) {
            int col = block_col + tx * TN + j;
            float2 v = unpack2(acc2[i][j]);
            float bb = bias[col];
            v.x += bb; v.y += bb;
            if (mode == 0) {
                C[(size_t)r0 * N + col] = v.x;
                C[(size_t)r1 * N + col] = v.y;
            } else {
                int h = col >> 5, dc = col & 31;
                int b0i = r0 / QTOT, q0 = r0 - b0i * QTOT;
                int b1i = r1 / QTOT, q1 = r1 - b1i * QTOT;
                g_val[(((size_t)(b0i * HEADS + h)) * QTOT + q0) * DH + dc] = v.x;
                g_val[(((size_t)(b1i * HEADS + h)) * QTOT + q1) * DH + dc] = v.y;
            }
        }
    }
}

// ---------------------------------------------------------------------------
// Sampler v2: one block per (b,q).
// Stage 1: 128 threads (one per head x (level,point)) compute the 4 bilinear
//          taps (index + combined weight) once, into smem.
// Stage 2: 256 threads (warp = head, lane = channel) run a lean gather loop:
//          LDS.64 broadcast of (w, idx) + one LDG + one FFMA per tap.
// ---------------------------------------------------------------------------
__global__ __launch_bounds__(256, 8)
void sample_kernel(const float* __restrict__ ref,
                   float* __restrict__ mid)
{
    const int bq = blockIdx.x;            // 0 .. BS*QTOT-1
    const int b  = bq / QTOT;
    const int t  = threadIdx.x;           // 256

    __shared__ float  s_w[128];
    __shared__ float2 s_tap[512];         // [h][16 pts][4 taps] = (w, idx bits)
    __shared__ float  s_ref[2 * LVLS];

    if (t < 128) s_w[t] = g_attn[(size_t)bq * 128 + t];
    if (t < 2 * LVLS) s_ref[t] = ref[(size_t)bq * (2 * LVLS) + t];
    __syncthreads();

    // per-head softmax over 16 logits
    if (t < HEADS) {
        float m = -1e30f;
        #pragma unroll
        for (int i = 0; i < 16; i++) m = fmaxf(m, s_w[t * 16 + i]);
        float s = 0.f;
        #pragma unroll
        for (int i = 0; i < 16; i++) {
            float e = expf(s_w[t * 16 + i] - m);
            s_w[t * 16 + i] = e;
            s += e;
        }
        float inv = 1.f / s;
        #pragma unroll
        for (int i = 0; i < 16; i++) s_w[t * 16 + i] *= inv;
    }
    __syncthreads();

    // Stage 1: tap computation (one thread per (h, l, p))
    if (t < 128) {
        const int h  = t >> 4;
        const int pt = t & 15;
        const int l  = pt >> 2;
        const int p  = pt & 3;

        const float ox = g_off[(size_t)bq * 256 + h * 32 + l * 8 + p * 2 + 0];
        const float oy = g_off[(size_t)bq * 256 + h * 32 + l * 8 + p * 2 + 1];
        const float aw = s_w[h * 16 + pt];

        const int   W   = c_lvl_wh[l];
        const int   st  = c_lvl_start[l];
        const float fW  = (float)W;
        const float inv = 1.0f / fW;      // exact: W is a power of two

        float x = (s_ref[l * 2 + 0] + ox * inv) * fW - 0.5f;
        float y = (s_ref[l * 2 + 1] + oy * inv) * fW - 0.5f;

        float x0f = floorf(x), y0f = floorf(y);
        int   x0 = (int)x0f,   y0 = (int)y0f;
        float fx = x - x0f,    fy = y - y0f;
        float gx = 1.f - fx,   gy = 1.f - fy;

        bool vx0 = (x0 >= 0)     & (x0 < W);
        bool vx1 = (x0 + 1 >= 0) & (x0 + 1 < W);
        bool vy0 = (y0 >= 0)     & (y0 < W);
        bool vy1 = (y0 + 1 >= 0) & (y0 + 1 < W);

        float w00 = (vx0 & vy0) ? gx * gy * aw : 0.f;
        float w10 = (vx1 & vy0) ? fx * gy * aw : 0.f;
        float w01 = (vx0 & vy1) ? gx * fy * aw : 0.f;
        float w11 = (vx1 & vy1) ? fx * fy * aw : 0.f;

        int i00 = (vx0 & vy0) ? st + y0 * W + x0           : st;
        int i10 = (vx1 & vy0) ? st + y0 * W + x0 + 1       : st;
        int i01 = (vx0 & vy1) ? st + (y0 + 1) * W + x0     : st;
        int i11 = (vx1 & vy1) ? st + (y0 + 1) * W + x0 + 1 : st;

        float2* tp = &s_tap[t * 4];
        tp[0] = make_float2(w00, __int_as_float(i00));
        tp[1] = make_float2(w10, __int_as_float(i10));
        tp[2] = make_float2(w01, __int_as_float(i01));
        tp[3] = make_float2(w11, __int_as_float(i11));
    }
    __syncthreads();

    // Stage 2: gather (warp = head, lane = channel)
    const int h  = t >> 5;
    const int dc = t & 31;
    const float* __restrict__ valb =
        g_val + ((size_t)(b * HEADS + h)) * QTOT * DH + dc;
    const float2* __restrict__ tap = &s_tap[h * 64];

    float a0 = 0.f, a1 = 0.f, a2 = 0.f, a3 = 0.f;
    #pragma unroll 16
    for (int k = 0; k < 64; k += 4) {
        float2 t0 = tap[k + 0];
        float2 t1 = tap[k + 1];
        float2 t2 = tap[k + 2];
        float2 t3 = tap[k + 3];
        a0 = fmaf(t0.x, valb[(size_t)__float_as_int(t0.y) * DH], a0);
        a1 = fmaf(t1.x, valb[(size_t)__float_as_int(t1.y) * DH], a1);
        a2 = fmaf(t2.x, valb[(size_t)__float_as_int(t2.y) * DH], a2);
        a3 = fmaf(t3.x, valb[(size_t)__float_as_int(t3.y) * DH], a3);
    }
    mid[(size_t)bq * 256 + t] = (a0 + a1) + (a2 + a3);
}

// ---------------------------------------------------------------------------
// Launch
// ---------------------------------------------------------------------------
extern "C" void kernel_launch(void* const* d_in, const int* in_sizes, int n_in,
                              void* d_out, int out_size)
{
    const float* query  = (const float*)d_in[0];
    const float* value  = (const float*)d_in[1];
    const float* refpts = (const float*)d_in[2];
    // d_in[3] = spatial_shapes (compile-time constants here)
    const float* W_off  = (const float*)d_in[4];
    const float* b_off  = (const float*)d_in[5];
    const float* W_attn = (const float*)d_in[6];
    const float* b_attn = (const float*)d_in[7];
    const float* W_v    = (const float*)d_in[8];
    const float* b_v    = (const float*)d_in[9];
    const float* W_out  = (const float*)d_in[10];
    const float* b_out  = (const float*)d_in[11];
    float* out = (float*)d_out;

    float *p_val, *p_off, *p_attn, *p_mid;
    cudaGetSymbolAddress((void**)&p_val,  g_val);
    cudaGetSymbolAddress((void**)&p_off,  g_off);
    cudaGetSymbolAddress((void**)&p_attn, g_attn);
    cudaGetSymbolAddress((void**)&p_mid,  g_mid);

    dim3 blk(256);
    dim3 grid256(CEMB / BN, MTOT / BM);   // (2, 340)
    dim3 grid128(128 / BN,  MTOT / BM);   // (1, 340)

    // 1) val = value @ W_v + b_v  -> [b][h][v][d] layout
    sgemm2_kernel<<<grid256, blk>>>(value, W_v, b_v, p_val, MTOT, CEMB, CEMB, 1);
    // 2) off = query @ W_off + b_off
    sgemm2_kernel<<<grid256, blk>>>(query, W_off, b_off, p_off, MTOT, CEMB, CEMB, 0);
    // 3) attn logits = query @ W_attn + b_attn
    sgemm2_kernel<<<grid128, blk>>>(query, W_attn, b_attn, p_attn, MTOT, 128, CEMB, 0);
    // 4) deformable sampling -> g_mid
    sample_kernel<<<MTOT, blk>>>(refpts, p_mid);
    // 5) out = mid @ W_out + b_out
    sgemm2_kernel<<<grid256, blk>>>(p_mid, W_out, b_out, out, MTOT, CEMB, CEMB, 0);
}

// round 9
// speedup vs baseline: 2.4994x; 1.8207x over previous
#include <cuda_runtime.h>
#include <cuda_bf16.h>
#include <cstdint>

// ---------------------------------------------------------------------------
// Problem constants (fixed by the reference setup)
// ---------------------------------------------------------------------------
#define BS    2
#define QTOT  21760        // = V = sum of level areas
#define CEMB  256
#define HEADS 8
#define DH    32           // C / HEADS
#define LVLS  4
#define PTS   4
#define MTOT  (BS * QTOT)  // 43520 rows for all GEMMs

__device__ __constant__ int c_lvl_wh[LVLS]    = {128, 64, 32, 16};
__device__ __constant__ int c_lvl_start[LVLS] = {0, 16384, 20480, 21504};

// ---------------------------------------------------------------------------
// Scratch (static device globals; no runtime allocation)
// ---------------------------------------------------------------------------
__device__ __align__(16) float g_val [(size_t)BS * QTOT * CEMB];   // [b][h][v][d]
__device__ __align__(16) float g_off [(size_t)BS * QTOT * CEMB];   // [b][q][256]
__device__ __align__(16) float g_attn[(size_t)BS * QTOT * 128];    // [b][q][128]

// bf16 hi/lo split activations: 3 segments (value, query, mid), [M][256] each
#define SEGSZ ((size_t)MTOT * 256)
__device__ __align__(16) __nv_bfloat16 g_ahi[3 * SEGSZ];
__device__ __align__(16) __nv_bfloat16 g_alo[3 * SEGSZ];

// transposed + split weights: [N][K=256] bf16, hi and lo parts
#define WT_TOTAL 229376
__device__ __align__(16) __nv_bfloat16 g_bt_hi[WT_TOTAL];
__device__ __align__(16) __nv_bfloat16 g_bt_lo[WT_TOTAL];
#define OFF_WV    0
#define OFF_WOFF  65536
#define OFF_WATTN 131072
#define OFF_WOUT  163840

// ---------------------------------------------------------------------------
// sm_80-era PTX helpers (all legal for plain sm_103 target)
// ---------------------------------------------------------------------------
__device__ __forceinline__ uint32_t smem_u32(const void* p) {
    uint32_t a;
    asm("{ .reg .u64 t; cvta.to.shared.u64 t, %1; cvt.u32.u64 %0, t; }"
        : "=r"(a) : "l"(p));
    return a;
}
__device__ __forceinline__ void cpa16(uint32_t dst, const void* src) {
    asm volatile("cp.async.cg.shared.global [%0], [%1], 16;" :: "r"(dst), "l"(src));
}
#define CP_COMMIT() asm volatile("cp.async.commit_group;" ::: "memory")
#define CP_WAIT1()  asm volatile("cp.async.wait_group 1;"  ::: "memory")

__device__ __forceinline__ void ldsm4(uint32_t* r, uint32_t a) {
    asm volatile("ldmatrix.sync.aligned.m8n8.x4.shared.b16 {%0,%1,%2,%3}, [%4];"
                 : "=r"(r[0]), "=r"(r[1]), "=r"(r[2]), "=r"(r[3]) : "r"(a));
}
__device__ __forceinline__ void mma16816(float* c, const uint32_t* a,
                                         uint32_t b0, uint32_t b1) {
    asm volatile(
        "mma.sync.aligned.m16n8k16.row.col.f32.bf16.bf16.f32 "
        "{%0,%1,%2,%3}, {%4,%5,%6,%7}, {%8,%9}, {%0,%1,%2,%3};"
        : "+f"(c[0]), "+f"(c[1]), "+f"(c[2]), "+f"(c[3])
        : "r"(a[0]), "r"(a[1]), "r"(a[2]), "r"(a[3]), "r"(b0), "r"(b1));
}

// ---------------------------------------------------------------------------
// Weight convert: W[K=256][N] fp32 -> transposed [N][256] bf16 hi/lo
// ---------------------------------------------------------------------------
__global__ void convert_w_kernel(const float* __restrict__ w0, const float* __restrict__ w1,
                                 const float* __restrict__ w2, const float* __restrict__ w3)
{
    const int id = blockIdx.y;
    const float* src = (id == 0) ? w0 : (id == 1) ? w1 : (id == 2) ? w2 : w3;
    const int N    = (id == 2) ? 128 : 256;
    const int off  = (id == 0) ? OFF_WV : (id == 1) ? OFF_WOFF
                   : (id == 2) ? OFF_WATTN : OFF_WOUT;
    const int tot  = 256 * N;
    int i = blockIdx.x * blockDim.x + threadIdx.x;
    if (i >= tot) return;
    int k = i / N, n = i - k * N;
    float x = src[i];
    __nv_bfloat16 hi = __float2bfloat16(x);
    __nv_bfloat16 lo = __float2bfloat16(x - __bfloat162float(hi));
    g_bt_hi[off + n * 256 + k] = hi;
    g_bt_lo[off + n * 256 + k] = lo;
}

// ---------------------------------------------------------------------------
// Activation convert: [M][256] fp32 -> bf16 hi/lo (vectorized)
// ---------------------------------------------------------------------------
__global__ void convert_a_kernel(const float4* __restrict__ src,
                                 __nv_bfloat162* __restrict__ hi,
                                 __nv_bfloat162* __restrict__ lo, int n4)
{
    int i = blockIdx.x * blockDim.x + threadIdx.x;
    if (i >= n4) return;
    float4 v = src[i];
    __nv_bfloat162 h01 = __floats2bfloat162_rn(v.x, v.y);
    __nv_bfloat162 h23 = __floats2bfloat162_rn(v.z, v.w);
    __nv_bfloat162 l01 = __floats2bfloat162_rn(v.x - __low2float(h01),
                                               v.y - __high2float(h01));
    __nv_bfloat162 l23 = __floats2bfloat162_rn(v.z - __low2float(h23),
                                               v.w - __high2float(h23));
    hi[i * 2]     = h01;
    hi[i * 2 + 1] = h23;
    lo[i * 2]     = l01;
    lo[i * 2 + 1] = l23;
}

// ---------------------------------------------------------------------------
// HMMA split-bf16 GEMM.
// C[128 x 128 tile] = A[M x 256] @ W[256 x NTtot] + bias, exact-ish via
// K' = 768 concatenation: kc 0-3: Ahi*Bhi, 4-7: Alo*Bhi, 8-11: Ahi*Blo.
// A: [M][256] bf16 row-major (hi/lo).  B: [N][256] bf16 (= W^T) hi/lo.
// 8 warps, warp tile 32x64, 3-stage cp.async pipeline, xor-swizzled smem.
// MODE 0: C row-major [M][ldc];  MODE 1: g_val permuted layout.
// ---------------------------------------------------------------------------
#define KC      64
#define NCHUNK  12
#define STAGEB  32768       // A 16KB + B 16KB per stage
#define NSTAGE  3

template <int MODE>
__global__ __launch_bounds__(256)
void gemm_hmma(const __nv_bfloat16* __restrict__ Ahi,
               const __nv_bfloat16* __restrict__ Alo,
               const __nv_bfloat16* __restrict__ Bhi,
               const __nv_bfloat16* __restrict__ Blo,
               const float* __restrict__ bias,
               float* __restrict__ C, int ldc)
{
    extern __shared__ __align__(128) char smem[];
    const uint32_t su = smem_u32(smem);

    const int tid  = threadIdx.x;
    const int lane = tid & 31;
    const int wid  = tid >> 5;
    const int wm   = wid & 3;          // 4 warps along M (32 rows each)
    const int wn   = wid >> 2;         // 2 warps along N (64 cols each)
    const int row0    = blockIdx.y * 128;
    const int colbase = blockIdx.x * 128;

    float acc[2][8][4];
    #pragma unroll
    for (int i = 0; i < 2; i++)
        #pragma unroll
        for (int j = 0; j < 8; j++)
            #pragma unroll
            for (int k = 0; k < 4; k++) acc[i][j][k] = 0.f;

    // ---- async stage loader: 2048 16B chunks (A then B), 8 per thread
    auto issue = [&](int kc, int s) {
        if (kc < NCHUNK) {
            const __nv_bfloat16* Asrc = (kc >= 4 && kc < 8) ? Alo : Ahi;
            const __nv_bfloat16* Bsrc = (kc < 8) ? Bhi : Blo;
            const int k0 = (kc & 3) * KC;
            const uint32_t sa = su + s * STAGEB;
            const uint32_t sb = sa + 16384;
            #pragma unroll
            for (int i = 0; i < 4; i++) {
                int idx = tid + i * 256;
                int r = idx >> 3, c = idx & 7;
                uint32_t sw = (uint32_t)((c ^ (r & 7)) << 4);
                cpa16(sa + r * 128 + sw,
                      Asrc + (size_t)(row0 + r) * 256 + k0 + c * 8);
                cpa16(sb + r * 128 + sw,
                      Bsrc + (size_t)(colbase + r) * 256 + k0 + c * 8);
            }
        }
        CP_COMMIT();
    };

    issue(0, 0);
    issue(1, 1);

    for (int kc = 0; kc < NCHUNK; kc++) {
        CP_WAIT1();
        __syncthreads();
        issue(kc + 2, (kc + 2) % NSTAGE);

        const uint32_t sa = su + (kc % NSTAGE) * STAGEB;
        const uint32_t sb = sa + 16384;

        #pragma unroll
        for (int kk = 0; kk < 4; kk++) {
            uint32_t af[2][4];
            #pragma unroll
            for (int tm = 0; tm < 2; tm++) {
                int r  = wm * 32 + tm * 16 + (lane & 15);
                int ch = kk * 2 + (lane >> 4);
                ldsm4(af[tm], sa + r * 128 + ((ch ^ (r & 7)) << 4));
            }
            uint32_t bf[4][4];
            #pragma unroll
            for (int tn = 0; tn < 4; tn++) {
                int r  = wn * 64 + tn * 16 + (lane & 15);
                int ch = kk * 2 + (lane >> 4);
                ldsm4(bf[tn], sb + r * 128 + ((ch ^ (r & 7)) << 4));
            }
            #pragma unroll
            for (int tm = 0; tm < 2; tm++)
                #pragma unroll
                for (int n8 = 0; n8 < 8; n8++) {
                    int tn = n8 >> 1, half = n8 & 1;
                    mma16816(acc[tm][n8], af[tm], bf[tn][half], bf[tn][half + 2]);
                }
        }
        __syncthreads();
    }

    // ---- epilogue (note: QTOT % 128 == 0, so a 128-row tile never crosses b)
    #pragma unroll
    for (int tm = 0; tm < 2; tm++) {
        const int gr = row0 + wm * 32 + tm * 16 + (lane >> 2);
        #pragma unroll
        for (int n8 = 0; n8 < 8; n8++) {
            const int col = colbase + wn * 64 + n8 * 8 + (lane & 3) * 2;
            float2 bb = *(const float2*)(bias + col);
            float2 v0 = make_float2(acc[tm][n8][0] + bb.x, acc[tm][n8][1] + bb.y);
            float2 v1 = make_float2(acc[tm][n8][2] + bb.x, acc[tm][n8][3] + bb.y);
            if (MODE == 0) {
                *(float2*)(C + (size_t)gr * ldc + col)       = v0;
                *(float2*)(C + (size_t)(gr + 8) * ldc + col) = v1;
            } else {
                int h = col >> 5, dc = col & 31;
                int b = gr / QTOT, q = gr - b * QTOT;
                size_t base = (((size_t)(b * HEADS + h)) * QTOT + q) * DH + dc;
                *(float2*)(g_val + base)           = v0;
                *(float2*)(g_val + base + 8 * DH)  = v1;
            }
        }
    }
}

// ---------------------------------------------------------------------------
// Sampler: one block per (b,q); taps precomputed in smem (R4 version).
// Writes mid directly as bf16 hi/lo into g_ahi/g_alo segment 2.
// ---------------------------------------------------------------------------
__global__ __launch_bounds__(256, 8)
void sample_kernel(const float* __restrict__ ref)
{
    const int bq = blockIdx.x;
    const int b  = bq / QTOT;
    const int t  = threadIdx.x;

    __shared__ float  s_w[128];
    __shared__ float2 s_tap[512];
    __shared__ float  s_ref[2 * LVLS];

    if (t < 128) s_w[t] = g_attn[(size_t)bq * 128 + t];
    if (t < 2 * LVLS) s_ref[t] = ref[(size_t)bq * (2 * LVLS) + t];
    __syncthreads();

    if (t < HEADS) {
        float m = -1e30f;
        #pragma unroll
        for (int i = 0; i < 16; i++) m = fmaxf(m, s_w[t * 16 + i]);
        float s = 0.f;
        #pragma unroll
        for (int i = 0; i < 16; i++) {
            float e = expf(s_w[t * 16 + i] - m);
            s_w[t * 16 + i] = e;
            s += e;
        }
        float inv = 1.f / s;
        #pragma unroll
        for (int i = 0; i < 16; i++) s_w[t * 16 + i] *= inv;
    }
    __syncthreads();

    if (t < 128) {
        const int h  = t >> 4;
        const int pt = t & 15;
        const int l  = pt >> 2;
        const int p  = pt & 3;

        const float ox = g_off[(size_t)bq * 256 + h * 32 + l * 8 + p * 2 + 0];
        const float oy = g_off[(size_t)bq * 256 + h * 32 + l * 8 + p * 2 + 1];
        const float aw = s_w[h * 16 + pt];

        const int   W   = c_lvl_wh[l];
        const int   st  = c_lvl_start[l];
        const float fW  = (float)W;
        const float inv = 1.0f / fW;

        float x = (s_ref[l * 2 + 0] + ox * inv) * fW - 0.5f;
        float y = (s_ref[l * 2 + 1] + oy * inv) * fW - 0.5f;

        float x0f = floorf(x), y0f = floorf(y);
        int   x0 = (int)x0f,   y0 = (int)y0f;
        float fx = x - x0f,    fy = y - y0f;
        float gx = 1.f - fx,   gy = 1.f - fy;

        bool vx0 = (x0 >= 0)     & (x0 < W);
        bool vx1 = (x0 + 1 >= 0) & (x0 + 1 < W);
        bool vy0 = (y0 >= 0)     & (y0 < W);
        bool vy1 = (y0 + 1 >= 0) & (y0 + 1 < W);

        float w00 = (vx0 & vy0) ? gx * gy * aw : 0.f;
        float w10 = (vx1 & vy0) ? fx * gy * aw : 0.f;
        float w01 = (vx0 & vy1) ? gx * fy * aw : 0.f;
        float w11 = (vx1 & vy1) ? fx * fy * aw : 0.f;

        int i00 = (vx0 & vy0) ? st + y0 * W + x0           : st;
        int i10 = (vx1 & vy0) ? st + y0 * W + x0 + 1       : st;
        int i01 = (vx0 & vy1) ? st + (y0 + 1) * W + x0     : st;
        int i11 = (vx1 & vy1) ? st + (y0 + 1) * W + x0 + 1 : st;

        float2* tp = &s_tap[t * 4];
        tp[0] = make_float2(w00, __int_as_float(i00));
        tp[1] = make_float2(w10, __int_as_float(i10));
        tp[2] = make_float2(w01, __int_as_float(i01));
        tp[3] = make_float2(w11, __int_as_float(i11));
    }
    __syncthreads();

    const int h  = t >> 5;
    const int dc = t & 31;
    const float* __restrict__ valb =
        g_val + ((size_t)(b * HEADS + h)) * QTOT * DH + dc;
    const float2* __restrict__ tap = &s_tap[h * 64];

    float a0 = 0.f, a1 = 0.f, a2 = 0.f, a3 = 0.f;
    #pragma unroll 16
    for (int k = 0; k < 64; k += 4) {
        float2 t0 = tap[k + 0];
        float2 t1 = tap[k + 1];
        float2 t2 = tap[k + 2];
        float2 t3 = tap[k + 3];
        a0 = fmaf(t0.x, valb[(size_t)__float_as_int(t0.y) * DH], a0);
        a1 = fmaf(t1.x, valb[(size_t)__float_as_int(t1.y) * DH], a1);
        a2 = fmaf(t2.x, valb[(size_t)__float_as_int(t2.y) * DH], a2);
        a3 = fmaf(t3.x, valb[(size_t)__float_as_int(t3.y) * DH], a3);
    }
    float v = (a0 + a1) + (a2 + a3);
    __nv_bfloat16 hv = __float2bfloat16(v);
    __nv_bfloat16 lv = __float2bfloat16(v - __bfloat162float(hv));
    g_ahi[2 * SEGSZ + (size_t)bq * 256 + t] = hv;
    g_alo[2 * SEGSZ + (size_t)bq * 256 + t] = lv;
}

// ---------------------------------------------------------------------------
// Launch
// ---------------------------------------------------------------------------
extern "C" void kernel_launch(void* const* d_in, const int* in_sizes, int n_in,
                              void* d_out, int out_size)
{
    const float* query  = (const float*)d_in[0];
    const float* value  = (const float*)d_in[1];
    const float* refpts = (const float*)d_in[2];
    // d_in[3] = spatial_shapes (compile-time constants here)
    const float* W_off  = (const float*)d_in[4];
    const float* b_off  = (const float*)d_in[5];
    const float* W_attn = (const float*)d_in[6];
    const float* b_attn = (const float*)d_in[7];
    const float* W_v    = (const float*)d_in[8];
    const float* b_v    = (const float*)d_in[9];
    const float* W_out  = (const float*)d_in[10];
    const float* b_out  = (const float*)d_in[11];
    float* out = (float*)d_out;

    float *p_off, *p_attn;
    __nv_bfloat16 *p_ahi, *p_alo, *p_bh, *p_bl;
    cudaGetSymbolAddress((void**)&p_off,  g_off);
    cudaGetSymbolAddress((void**)&p_attn, g_attn);
    cudaGetSymbolAddress((void**)&p_ahi,  g_ahi);
    cudaGetSymbolAddress((void**)&p_alo,  g_alo);
    cudaGetSymbolAddress((void**)&p_bh,   g_bt_hi);
    cudaGetSymbolAddress((void**)&p_bl,   g_bt_lo);

    const int SMEMSZ = NSTAGE * STAGEB;   // 98304
    static bool attr_done = false;
    if (!attr_done) {
        cudaFuncSetAttribute(gemm_hmma<0>,
                             cudaFuncAttributeMaxDynamicSharedMemorySize, SMEMSZ);
        cudaFuncSetAttribute(gemm_hmma<1>,
                             cudaFuncAttributeMaxDynamicSharedMemorySize, SMEMSZ);
        attr_done = true;
    }

    const int N4 = (int)(SEGSZ / 4);          // 2,785,280 float4s
    dim3 blk(256);
    dim3 grid2(2, MTOT / 128);                // 256-wide GEMMs
    dim3 grid1(1, MTOT / 128);                // 128-wide GEMM

    // 0) weight + activation converts
    convert_w_kernel<<<dim3(128, 4), 512>>>(W_v, W_off, W_attn, W_out);
    convert_a_kernel<<<N4 / 256, blk>>>((const float4*)value,
                                        (__nv_bfloat162*)p_ahi,
                                        (__nv_bfloat162*)p_alo, N4);
    convert_a_kernel<<<N4 / 256, blk>>>((const float4*)query,
                                        (__nv_bfloat162*)(p_ahi + SEGSZ),
                                        (__nv_bfloat162*)(p_alo + SEGSZ), N4);

    // 1) val = value @ W_v + b_v  -> g_val permuted layout
    gemm_hmma<1><<<grid2, blk, SMEMSZ>>>(p_ahi, p_alo,
                                         p_bh + OFF_WV, p_bl + OFF_WV,
                                         b_v, nullptr, 256);
    // 2) off = query @ W_off + b_off
    gemm_hmma<0><<<grid2, blk, SMEMSZ>>>(p_ahi + SEGSZ, p_alo + SEGSZ,
                                         p_bh + OFF_WOFF, p_bl + OFF_WOFF,
                                         b_off, p_off, 256);
    // 3) attn logits = query @ W_attn + b_attn
    gemm_hmma<0><<<grid1, blk, SMEMSZ>>>(p_ahi + SEGSZ, p_alo + SEGSZ,
                                         p_bh + OFF_WATTN, p_bl + OFF_WATTN,
                                         b_attn, p_attn, 128);
    // 4) deformable sampling -> mid (bf16 hi/lo, segment 2)
    sample_kernel<<<MTOT, blk>>>(refpts);
    // 5) out = mid @ W_out + b_out
    gemm_hmma<0><<<grid2, blk, SMEMSZ>>>(p_ahi + 2 * SEGSZ, p_alo + 2 * SEGSZ,
                                         p_bh + OFF_WOUT, p_bl + OFF_WOUT,
                                         b_out, out, 256);
}